// round 15
// baseline (speedup 1.0000x reference)
#include <cuda_runtime.h>

// QuantumConvLayer: out[:,2i]   = cos(q[2i]) * cos(pi*x[:,2i])
//                   out[:,2i+1] = out[:,2i]  * cos(q[2i+1] + pi*x[:,2i+1])
// Streaming HBM-bound: 256MB read + 256MB write, zero reuse.
//
// R15: grid=2048 retried WITHOUT R14's self-inflicted serialization.
// R14's two-phase layout put stores (asm "memory" clobber) between the
// load pairs, blocking hoist -> effective MLP=2. Here: all FOUR 256-bit
// loads front-batched (no clobber on loads), compute IN PLACE (results
// overwrite v regs; live set ~50 regs < 64-reg cap @ TPB=1024), then
// store per chunk. 128B in flight per thread, 128KB contiguous per CTA
// per direction. Exact grid (2048), shared row phase, one q pair/thread.
// Bench gradient so far: 65536blk=82.4 -> 8192=81.6 -> 4096=80.13 (best).

#ifndef QC_PI
#define QC_PI 3.14159265358979323846f
#endif

#define TPB 1024  // threads per block
#define CPT 4     // 8-float chunks per thread
#define TILE_CH (TPB * CPT)   // 4096 chunks (32768 floats) per block

__device__ __forceinline__ void ldg256_ef(const float* p, float r[8])
{
    asm volatile("ld.global.nc.L2::evict_first.v8.f32 "
                 "{%0,%1,%2,%3,%4,%5,%6,%7}, [%8];"
                 : "=f"(r[0]), "=f"(r[1]), "=f"(r[2]), "=f"(r[3]),
                   "=f"(r[4]), "=f"(r[5]), "=f"(r[6]), "=f"(r[7])
                 : "l"(p));
}

__device__ __forceinline__ void stg256_ef(float* p, const float r[8])
{
    asm volatile("st.global.L2::evict_first.v8.f32 "
                 "[%0], {%1,%2,%3,%4,%5,%6,%7,%8};"
                 :: "l"(p),
                    "f"(r[0]), "f"(r[1]), "f"(r[2]), "f"(r[3]),
                    "f"(r[4]), "f"(r[5]), "f"(r[6]), "f"(r[7])
                 : "memory");
}

// compute in place: v[] becomes the output chunk
__device__ __forceinline__ void qc_chunk_ip(float v[8],
                                            float ca, float cb, float cc, float cd,
                                            float qay, float qaw, float qby, float qbw)
{
    v[0] = ca * __cosf(QC_PI * v[0]);
    v[1] = v[0] * __cosf(fmaf(QC_PI, v[1], qay));
    v[2] = cb * __cosf(QC_PI * v[2]);
    v[3] = v[2] * __cosf(fmaf(QC_PI, v[3], qaw));
    v[4] = cc * __cosf(QC_PI * v[4]);
    v[5] = v[4] * __cosf(fmaf(QC_PI, v[5], qby));
    v[6] = cd * __cosf(QC_PI * v[6]);
    v[7] = v[6] * __cosf(fmaf(QC_PI, v[7], qbw));
}

__global__ void __launch_bounds__(TPB)
qconv_kernel(const float* __restrict__ x,
             const float* __restrict__ q,
             float* __restrict__ out)
{
    int c0 = blockIdx.x * TILE_CH + threadIdx.x;   // chunks at +0,+TPB,+2TPB,+3TPB

    // all chunk offsets are multiples of TPB=1024 (even) -> shared row phase
    const float4* q4 = (const float4*)q;
    int ph = (c0 & 1) << 1;            // 0 or 2 (float4 index)
    float4 qa = __ldg(q4 + ph);        // q[8p .. 8p+3]
    float4 qb = __ldg(q4 + ph + 1);    // q[8p+4 .. 8p+7]

    float ca = __cosf(qa.x);
    float cb = __cosf(qa.z);
    float cc = __cosf(qb.x);
    float cd = __cosf(qb.z);

    // ALL loads front-batched: 128B in flight per thread, nothing blocks them
    float v0[8], v1[8], v2[8], v3[8];
    ldg256_ef(x + (size_t)(c0 + 0 * TPB) * 8, v0);
    ldg256_ef(x + (size_t)(c0 + 1 * TPB) * 8, v1);
    ldg256_ef(x + (size_t)(c0 + 2 * TPB) * 8, v2);
    ldg256_ef(x + (size_t)(c0 + 3 * TPB) * 8, v3);

    // compute in place, store as each chunk completes
    qc_chunk_ip(v0, ca, cb, cc, cd, qa.y, qa.w, qb.y, qb.w);
    stg256_ef(out + (size_t)(c0 + 0 * TPB) * 8, v0);

    qc_chunk_ip(v1, ca, cb, cc, cd, qa.y, qa.w, qb.y, qb.w);
    stg256_ef(out + (size_t)(c0 + 1 * TPB) * 8, v1);

    qc_chunk_ip(v2, ca, cb, cc, cd, qa.y, qa.w, qb.y, qb.w);
    stg256_ef(out + (size_t)(c0 + 2 * TPB) * 8, v2);

    qc_chunk_ip(v3, ca, cb, cc, cd, qa.y, qa.w, qb.y, qb.w);
    stg256_ef(out + (size_t)(c0 + 3 * TPB) * 8, v3);
}

extern "C" void kernel_launch(void* const* d_in, const int* in_sizes, int n_in,
                              void* d_out, int out_size)
{
    const float* x = (const float*)d_in[0];
    const float* q = (const float*)d_in[1];
    float* out     = (float*)d_out;

    int n_elems  = in_sizes[0];     // B * 16 = 67108864
    int n_chunks = n_elems >> 3;    // 8388608 chunks; divisible by TILE_CH=4096

    int blocks = n_chunks / TILE_CH;   // 2048, exact
    qconv_kernel<<<blocks, TPB>>>(x, q, out);
}

// round 16
// speedup vs baseline: 1.0347x; 1.0347x over previous
#include <cuda_runtime.h>

// QuantumConvLayer: out[:,2i]   = cos(q[2i]) * cos(pi*x[:,2i])
//                   out[:,2i+1] = out[:,2i]  * cos(q[2i+1] + pi*x[:,2i+1])
// Streaming HBM-bound: 256MB read + 256MB write, zero reuse.
//
// R16 = R13 confirmation (best bench: 80.13us). Measured CTA-count curve:
//   65536blk 82.4 | 16384 82.3 | 8192 81.6 | 4096 80.13 | 2048 83.1
// -> minimum at grid=4096, TPB=1024, CPT=2, 256-bit evict-first accesses.
// All neighbors measured worse; re-bench to confirm the optimum per
// rigor.md before finalizing.

#ifndef QC_PI
#define QC_PI 3.14159265358979323846f
#endif

#define TPB 1024  // threads per block
#define CPT 2     // 8-float chunks per thread
#define TILE_CH (TPB * CPT)   // 2048 chunks (16384 floats) per block

__device__ __forceinline__ void ldg256_ef(const float* p, float r[8])
{
    asm volatile("ld.global.nc.L2::evict_first.v8.f32 "
                 "{%0,%1,%2,%3,%4,%5,%6,%7}, [%8];"
                 : "=f"(r[0]), "=f"(r[1]), "=f"(r[2]), "=f"(r[3]),
                   "=f"(r[4]), "=f"(r[5]), "=f"(r[6]), "=f"(r[7])
                 : "l"(p));
}

__device__ __forceinline__ void stg256_ef(float* p, const float r[8])
{
    asm volatile("st.global.L2::evict_first.v8.f32 "
                 "[%0], {%1,%2,%3,%4,%5,%6,%7,%8};"
                 :: "l"(p),
                    "f"(r[0]), "f"(r[1]), "f"(r[2]), "f"(r[3]),
                    "f"(r[4]), "f"(r[5]), "f"(r[6]), "f"(r[7])
                 : "memory");
}

__global__ void __launch_bounds__(TPB)
qconv_kernel(const float* __restrict__ x,
             const float* __restrict__ q,
             float* __restrict__ out)
{
    // chunk index: 8 floats per chunk, warp-contiguous (lane i -> 32B apart)
    int c0 = blockIdx.x * TILE_CH + threadIdx.x;
    int c1 = c0 + TPB;

    // two 256-bit loads front-batched (64B in flight per thread)
    float v0[8], v1[8];
    ldg256_ef(x + (size_t)c0 * 8, v0);
    ldg256_ef(x + (size_t)c1 * 8, v1);

    // chunk c covers columns (8c .. 8c+7) mod 16 -> phase = c & 1.
    // TPB=1024 even -> c0, c1 share phase. One pair of q float4 loads.
    const float4* q4 = (const float4*)q;
    int ph = (c0 & 1) << 1;            // 0 or 2 (float4 index)
    float4 qa = __ldg(q4 + ph);        // q[8p .. 8p+3]
    float4 qb = __ldg(q4 + ph + 1);    // q[8p+4 .. 8p+7]

    float ca = __cosf(qa.x);   // cos(q[c+0])
    float cb = __cosf(qa.z);   // cos(q[c+2])
    float cc = __cosf(qb.x);   // cos(q[c+4])
    float cd = __cosf(qb.z);   // cos(q[c+6])

    float r0[8], r1[8];

    r0[0] = ca * __cosf(QC_PI * v0[0]);
    r0[1] = r0[0] * __cosf(fmaf(QC_PI, v0[1], qa.y));
    r0[2] = cb * __cosf(QC_PI * v0[2]);
    r0[3] = r0[2] * __cosf(fmaf(QC_PI, v0[3], qa.w));
    r0[4] = cc * __cosf(QC_PI * v0[4]);
    r0[5] = r0[4] * __cosf(fmaf(QC_PI, v0[5], qb.y));
    r0[6] = cd * __cosf(QC_PI * v0[6]);
    r0[7] = r0[6] * __cosf(fmaf(QC_PI, v0[7], qb.w));

    r1[0] = ca * __cosf(QC_PI * v1[0]);
    r1[1] = r1[0] * __cosf(fmaf(QC_PI, v1[1], qa.y));
    r1[2] = cb * __cosf(QC_PI * v1[2]);
    r1[3] = r1[2] * __cosf(fmaf(QC_PI, v1[3], qa.w));
    r1[4] = cc * __cosf(QC_PI * v1[4]);
    r1[5] = r1[4] * __cosf(fmaf(QC_PI, v1[5], qb.y));
    r1[6] = cd * __cosf(QC_PI * v1[6]);
    r1[7] = r1[6] * __cosf(fmaf(QC_PI, v1[7], qb.w));

    stg256_ef(out + (size_t)c0 * 8, r0);
    stg256_ef(out + (size_t)c1 * 8, r1);
}

extern "C" void kernel_launch(void* const* d_in, const int* in_sizes, int n_in,
                              void* d_out, int out_size)
{
    const float* x = (const float*)d_in[0];
    const float* q = (const float*)d_in[1];
    float* out     = (float*)d_out;

    int n_elems  = in_sizes[0];     // B * 16 = 67108864
    int n_chunks = n_elems >> 3;    // 8388608 chunks; divisible by TILE_CH=2048

    int blocks = n_chunks / TILE_CH;   // 4096, exact
    qconv_kernel<<<blocks, TPB>>>(x, q, out);
}